// round 1
// baseline (speedup 1.0000x reference)
#include <cuda_runtime.h>
#include <math.h>

#define Bn 128
#define Cn 48
#define Hn 64
#define Wn 64
#define Pn 32
#define OUT_ELEMS (Bn*Cn*Hn*Wn)

// Scratch (no allocations allowed)
__device__ float g_M[Cn*Cn];          // combined bilinear matrix (includes 1/scale)
__device__ float g_Spart[512*4];      // per-block score partials: bid=(b*4+g*2+ih)
__device__ float g_A[Bn*2*4];         // attn coefficients per (b, group): a_tt,a_tb,a_bt,a_bb

// ---------------------------------------------------------------------------
// Kernel A: M[c][c2] = sum_o (Wq1[o,c]Wk1[o,c2] + Wq2..Wk2 + Wq3..Wk3) / sqrt(C*p*p)
// ---------------------------------------------------------------------------
__global__ void prep_kernel(const float* __restrict__ Wq1, const float* __restrict__ Wq2,
                            const float* __restrict__ Wq3, const float* __restrict__ Wk1,
                            const float* __restrict__ Wk2, const float* __restrict__ Wk3) {
    int idx = blockIdx.x * blockDim.x + threadIdx.x;
    if (idx >= Cn*Cn) return;
    int c = idx / Cn, c2 = idx % Cn;
    float s = 0.f;
    for (int o = 0; o < Cn; ++o) {
        s += Wq1[o*Cn+c]*Wk1[o*Cn+c2]
           + Wq2[o*Cn+c]*Wk2[o*Cn+c2]
           + Wq3[o*Cn+c]*Wk3[o*Cn+c2];
    }
    g_M[idx] = s * (1.0f / sqrtf((float)(Cn*Pn*Pn)));
}

// ---------------------------------------------------------------------------
// Kernel B: scores. One block per (b, group, i-half). group g in {0,1}:
//   patches {g, g+2} = (top,bottom) halves of column-block g. Only columns with
//   j parity == g contribute (mask). Computes partial S_tt,S_tb,S_bt,S_bb.
// ---------------------------------------------------------------------------
__global__ __launch_bounds__(256, 2) void score_kernel(const float* __restrict__ x) {
    __shared__ float sM[Cn*Cn];            // 9216 B
    __shared__ float tile[8*32*33];        // 33792 B staging: [cc][row32][col(+pad)]
    __shared__ float sred[8][4];

    int bid = blockIdx.x;
    int b  = bid >> 2;
    int g  = (bid >> 1) & 1;
    int ih = bid & 1;
    int tid = threadIdx.x;

    for (int i = tid; i < Cn*Cn; i += 256) sM[i] = g_M[i];

    int i_loc = tid >> 4;          // 0..15 local row
    int jj    = tid & 15;
    int j     = 2*jj + g;          // masked column within patch
    const float* xb_base = x + (size_t)b * Cn * Hn * Wn;

    float vt[Cn], vb[Cn];

    #pragma unroll
    for (int ch = 0; ch < 6; ++ch) {
        __syncthreads();
        // stage 8 channels x 32 rows (16 top + 16 bottom) x 32 cols, coalesced float4
        #pragma unroll
        for (int k = 0; k < 8; ++k) {
            int idx  = tid + k*256;
            int col4 = idx & 7;
            int r    = (idx >> 3) & 31;
            int cc   = idx >> 8;
            int c    = ch*8 + cc;
            int y    = (r < 16) ? (ih*16 + r) : (32 + ih*16 + (r - 16));
            const float4 v = *(const float4*)(xb_base + ((size_t)c*Hn + y)*Wn + g*32 + col4*4);
            float* d = &tile[cc*(32*33) + r*33 + col4*4];
            d[0] = v.x; d[1] = v.y; d[2] = v.z; d[3] = v.w;
        }
        __syncthreads();
        #pragma unroll
        for (int cc = 0; cc < 8; ++cc) {
            vt[ch*8+cc] = tile[cc*(32*33) + i_loc*33 + j];
            vb[ch*8+cc] = tile[cc*(32*33) + (16+i_loc)*33 + j];
        }
    }

    float p00=0.f, p01=0.f, p10=0.f, p11=0.f;
    #pragma unroll
    for (int c = 0; c < Cn; ++c) {
        float rt = 0.f, rb = 0.f;
        #pragma unroll
        for (int c2 = 0; c2 < Cn; ++c2) {
            float m = sM[c*Cn + c2];     // warp-uniform broadcast LDS
            rt += m * vt[c2];
            rb += m * vb[c2];
        }
        p00 += vt[c]*rt;  p01 += vt[c]*rb;
        p10 += vb[c]*rt;  p11 += vb[c]*rb;
    }

    // deterministic block reduction (no atomics)
    #pragma unroll
    for (int off = 16; off; off >>= 1) {
        p00 += __shfl_xor_sync(0xffffffffu, p00, off);
        p01 += __shfl_xor_sync(0xffffffffu, p01, off);
        p10 += __shfl_xor_sync(0xffffffffu, p10, off);
        p11 += __shfl_xor_sync(0xffffffffu, p11, off);
    }
    int wid = tid >> 5;
    if ((tid & 31) == 0) {
        sred[wid][0]=p00; sred[wid][1]=p01; sred[wid][2]=p10; sred[wid][3]=p11;
    }
    __syncthreads();
    if (tid == 0) {
        float s0=0,s1=0,s2=0,s3=0;
        #pragma unroll
        for (int w = 0; w < 8; ++w) { s0+=sred[w][0]; s1+=sred[w][1]; s2+=sred[w][2]; s3+=sred[w][3]; }
        float* s = &g_Spart[bid*4];
        s[0]=s0; s[1]=s1; s[2]=s2; s[3]=s3;
    }
}

// ---------------------------------------------------------------------------
// Kernel C: softmax over 4 entries (2 real + 2 exact zeros), attn coeffs,
//           2x2 logdets, logdet output.
// ---------------------------------------------------------------------------
__global__ void attn_kernel(const float* __restrict__ logdet_in,
                            const float* __restrict__ off1p,
                            const float* __restrict__ off2p,
                            const float* __restrict__ off3p,
                            float* __restrict__ out, int out_size) {
    int b = threadIdx.x;
    if (b >= Bn) return;
    const float off  = off1p[0];
    const float off2 = off2p[0];
    const float off3 = off3p[0];
    float ld = logdet_in[b];

    #pragma unroll
    for (int g = 0; g < 2; ++g) {
        const float* s0 = &g_Spart[(b*4 + g*2 + 0)*4];
        const float* s1 = &g_Spart[(b*4 + g*2 + 1)*4];
        float stt = s0[0]+s1[0] + off3;
        float stb = s0[1]+s1[1] + off3;
        float sbt = s0[2]+s1[2] + off3;
        float sbb = s0[3]+s1[3] + off3;
        float z = off3;  // the two masked-out (zero score) entries per row

        float mx   = fmaxf(fmaxf(stt, stb), z);
        float e0   = expf(stt-mx), e1 = expf(stb-mx), ez = expf(z-mx);
        float inv  = 1.f / (e0 + e1 + 2.f*ez);
        float a_tt = e0*inv + off2 + off;
        float a_tb = e1*inv + off2;

        mx  = fmaxf(fmaxf(sbt, sbb), z);
        e0  = expf(sbt-mx); e1 = expf(sbb-mx); ez = expf(z-mx);
        inv = 1.f / (e0 + e1 + 2.f*ez);
        float a_bt = e0*inv + off2;
        float a_bb = e1*inv + off2 + off;

        float det = a_tt*a_bb - a_tb*a_bt;
        ld += logf(fabsf(det)) * (float)(Pn*(Pn/2)*Cn);

        float* a = &g_A[(b*2+g)*4];
        a[0]=a_tt; a[1]=a_tb; a[2]=a_bt; a[3]=a_bb;
    }
    if (OUT_ELEMS + b < out_size) out[OUT_ELEMS + b] = ld;
}

// ---------------------------------------------------------------------------
// Kernel D: output assembly. Each thread: one float4 of the top half + the
// paired float4 32 rows below. Pass-through where (g + lane-parity) even,
// 2x2 mix elsewhere. Memory bound: 100MB read + 100MB write.
// ---------------------------------------------------------------------------
__global__ __launch_bounds__(256) void out_kernel(const float* __restrict__ x,
                                                  float* __restrict__ out) {
    int t  = blockIdx.x * blockDim.x + threadIdx.x;    // 3,145,728 threads
    int x4 = t & 15;
    int y  = (t >> 4) & 31;
    int r  = t >> 9;
    int c  = r % Cn;
    int b  = r / Cn;
    int g  = x4 >> 3;                                   // column-block = group

    const float* A = &g_A[(b*2+g)*4];
    float a_tt = __ldg(&A[0]), a_tb = __ldg(&A[1]);
    float a_bt = __ldg(&A[2]), a_bb = __ldg(&A[3]);

    size_t base = (((size_t)b*Cn + c)*Hn + y)*Wn + x4*4;
    float4 xt = *(const float4*)(x + base);
    float4 xb = *(const float4*)(x + base + 32*Wn);
    float4 ot, ob;
    if (g == 0) {  // pass-through at even lane (x,z)
        ot.x = xt.x;                    ob.x = xb.x;
        ot.y = a_tt*xt.y + a_tb*xb.y;   ob.y = a_bt*xt.y + a_bb*xb.y;
        ot.z = xt.z;                    ob.z = xb.z;
        ot.w = a_tt*xt.w + a_tb*xb.w;   ob.w = a_bt*xt.w + a_bb*xb.w;
    } else {       // pass-through at odd lane (y,w)
        ot.x = a_tt*xt.x + a_tb*xb.x;   ob.x = a_bt*xt.x + a_bb*xb.x;
        ot.y = xt.y;                    ob.y = xb.y;
        ot.z = a_tt*xt.z + a_tb*xb.z;   ob.z = a_bt*xt.z + a_bb*xb.z;
        ot.w = xt.w;                    ob.w = xb.w;
    }
    *(float4*)(out + base)          = ot;
    *(float4*)(out + base + 32*Wn)  = ob;
}

// ---------------------------------------------------------------------------
extern "C" void kernel_launch(void* const* d_in, const int* in_sizes, int n_in,
                              void* d_out, int out_size) {
    const float* x      = (const float*)d_in[0];
    const float* logdet = (const float*)d_in[1];
    const float* Wq1    = (const float*)d_in[2];
    const float* Wq2    = (const float*)d_in[3];
    const float* Wq3    = (const float*)d_in[4];
    const float* Wk1    = (const float*)d_in[5];
    const float* Wk2    = (const float*)d_in[6];
    const float* Wk3    = (const float*)d_in[7];
    const float* off1   = (const float*)d_in[8];
    const float* off2   = (const float*)d_in[9];
    const float* off3   = (const float*)d_in[10];
    float* out = (float*)d_out;

    prep_kernel<<<9, 256>>>(Wq1, Wq2, Wq3, Wk1, Wk2, Wk3);
    score_kernel<<<512, 256>>>(x);
    attn_kernel<<<1, 128>>>(logdet, off1, off2, off3, out, out_size);
    out_kernel<<<12288, 256>>>(x, out);
}